// round 1
// baseline (speedup 1.0000x reference)
#include <cuda_runtime.h>
#include <math.h>

#define D_      768
#define DFF_    3072
#define S_      512
#define B_      16
#define H_      12
#define DH_     64
#define L_      6
#define MTOK    (B_ * S_)   // 8192
#define EPS_    1e-5f

// ---------------- scratch (device globals; no allocation allowed) -------------
__device__ float g_h [MTOK * D_];
__device__ float g_q [MTOK * D_];
__device__ float g_k [MTOK * D_];
__device__ float g_v [MTOK * D_];
__device__ float g_o [MTOK * D_];
__device__ float g_t [MTOK * D_];
__device__ float g_ff[MTOK * DFF_];

// ---------------- block reduction helpers ------------------------------------
__device__ __forceinline__ float block_sum(float v, float* sred) {
    #pragma unroll
    for (int o = 16; o > 0; o >>= 1) v += __shfl_xor_sync(0xffffffffu, v, o);
    int wid = threadIdx.x >> 5, lid = threadIdx.x & 31;
    int nw = (blockDim.x + 31) >> 5;
    __syncthreads();
    if (lid == 0) sred[wid] = v;
    __syncthreads();
    if (wid == 0) {
        float t = (lid < nw) ? sred[lid] : 0.f;
        #pragma unroll
        for (int o = 16; o > 0; o >>= 1) t += __shfl_xor_sync(0xffffffffu, t, o);
        if (lid == 0) sred[0] = t;
    }
    __syncthreads();
    return sred[0];
}

__device__ __forceinline__ float block_max(float v, float* sred) {
    #pragma unroll
    for (int o = 16; o > 0; o >>= 1) v = fmaxf(v, __shfl_xor_sync(0xffffffffu, v, o));
    int wid = threadIdx.x >> 5, lid = threadIdx.x & 31;
    int nw = (blockDim.x + 31) >> 5;
    __syncthreads();
    if (lid == 0) sred[wid] = v;
    __syncthreads();
    if (wid == 0) {
        float t = (lid < nw) ? sred[lid] : -INFINITY;
        #pragma unroll
        for (int o = 16; o > 0; o >>= 1) t = fmaxf(t, __shfl_xor_sync(0xffffffffu, t, o));
        if (lid == 0) sred[0] = t;
    }
    __syncthreads();
    return sred[0];
}

// ---------------- input projection: h = x@in_w + in_b + pos -------------------
__global__ __launch_bounds__(256) void input_proj_kernel(
    const float* __restrict__ x, const float* __restrict__ in_w,
    const float* __restrict__ in_b, const float* __restrict__ pos)
{
    int t = blockIdx.x;             // token
    int s = t & (S_ - 1);
    __shared__ float sx[32];
    if (threadIdx.x < 32) sx[threadIdx.x] = x[t * 32 + threadIdx.x];
    __syncthreads();
    for (int d = threadIdx.x; d < D_; d += 256) {
        float acc = in_b[d] + pos[s * D_ + d];
        #pragma unroll
        for (int kk = 0; kk < 32; kk++) acc = fmaf(sx[kk], in_w[kk * D_ + d], acc);
        g_h[t * D_ + d] = acc;
    }
}

// ---------------- SGEMM 128x128x8, 8x8 microtile, 256 threads -----------------
// C[M,N] = A[M,K] @ B[K,N] + bias[N]  (optional relu).  M = MTOK (divisible by 128),
// N, K divisible by 128 / 8 respectively.
__global__ __launch_bounds__(256) void gemm_kernel(
    const float* __restrict__ A, const float* __restrict__ Bw,
    const float* __restrict__ bias, float* __restrict__ C,
    int N, int K, int relu)
{
    __shared__ float As[8][128];
    __shared__ float Bs[8][128];

    int tid = threadIdx.x;
    int bm = blockIdx.y * 128;
    int bn = blockIdx.x * 128;
    int tx = tid & 15;        // 0..15 -> N cols tx*8..+7
    int ty = tid >> 4;        // 0..15 -> M rows ty*8..+7

    float acc[8][8];
    #pragma unroll
    for (int i = 0; i < 8; i++)
        #pragma unroll
        for (int j = 0; j < 8; j++) acc[i][j] = 0.f;

    int arow = tid >> 1;             // 0..127
    int akq  = (tid & 1) * 4;        // 0 or 4
    int bkk  = tid >> 5;             // 0..7
    int bcol = (tid & 31) * 4;       // 0..124

    const float* Aptr = A + (size_t)(bm + arow) * K + akq;
    const float* Bptr = Bw + (size_t)bkk * N + bn + bcol;

    for (int k0 = 0; k0 < K; k0 += 8) {
        float4 av = *(const float4*)(Aptr + k0);
        float4 bv = *(const float4*)(Bptr + (size_t)k0 * N);
        As[akq + 0][arow] = av.x;
        As[akq + 1][arow] = av.y;
        As[akq + 2][arow] = av.z;
        As[akq + 3][arow] = av.w;
        *(float4*)&Bs[bkk][bcol] = bv;
        __syncthreads();

        #pragma unroll
        for (int kk = 0; kk < 8; kk++) {
            float4 a0 = *(const float4*)&As[kk][ty * 8];
            float4 a1 = *(const float4*)&As[kk][ty * 8 + 4];
            float4 b0 = *(const float4*)&Bs[kk][tx * 8];
            float4 b1 = *(const float4*)&Bs[kk][tx * 8 + 4];
            float a[8] = {a0.x, a0.y, a0.z, a0.w, a1.x, a1.y, a1.z, a1.w};
            float b[8] = {b0.x, b0.y, b0.z, b0.w, b1.x, b1.y, b1.z, b1.w};
            #pragma unroll
            for (int i = 0; i < 8; i++)
                #pragma unroll
                for (int j = 0; j < 8; j++)
                    acc[i][j] = fmaf(a[i], b[j], acc[i][j]);
        }
        __syncthreads();
    }

    #pragma unroll
    for (int i = 0; i < 8; i++) {
        int m = bm + ty * 8 + i;
        #pragma unroll
        for (int j = 0; j < 8; j += 4) {
            float4 v;
            v.x = acc[i][j + 0] + bias[bn + tx * 8 + j + 0];
            v.y = acc[i][j + 1] + bias[bn + tx * 8 + j + 1];
            v.z = acc[i][j + 2] + bias[bn + tx * 8 + j + 2];
            v.w = acc[i][j + 3] + bias[bn + tx * 8 + j + 3];
            if (relu) {
                v.x = fmaxf(v.x, 0.f); v.y = fmaxf(v.y, 0.f);
                v.z = fmaxf(v.z, 0.f); v.w = fmaxf(v.w, 0.f);
            }
            *(float4*)&C[(size_t)m * N + bn + tx * 8 + j] = v;
        }
    }
}

// ---------------- attention: one block per (q, head, batch) -------------------
__global__ __launch_bounds__(128) void attn_kernel(const int* __restrict__ lens)
{
    int qi = blockIdx.x, hd = blockIdx.y, b = blockIdx.z;
    int len = lens[b];
    int tid = threadIdx.x;

    __shared__ float sq[DH_];
    __shared__ float sp[S_];
    __shared__ float sred[32];
    __shared__ float so[128];

    const float* qrow = g_q + ((size_t)(b * S_ + qi) * H_ + hd) * DH_;
    if (tid < DH_) sq[tid] = qrow[tid];
    __syncthreads();

    // pass 1: scores
    float lmax = -INFINITY;
    for (int kk = tid; kk < S_; kk += 128) {
        float sc;
        if (kk < len) {
            const float4* kr = (const float4*)(g_k + ((size_t)(b * S_ + kk) * H_ + hd) * DH_);
            float acc = 0.f;
            #pragma unroll
            for (int j = 0; j < 16; j++) {
                float4 kv = kr[j];
                float4 qv = *(const float4*)&sq[j * 4];
                acc += kv.x * qv.x + kv.y * qv.y + kv.z * qv.z + kv.w * qv.w;
            }
            sc = acc * 0.125f;   // 1/sqrt(64)
        } else {
            sc = -INFINITY;
        }
        sp[kk] = sc;
        lmax = fmaxf(lmax, sc);
    }
    float gmax = block_max(lmax, sred);

    // pass 2: exp + sum
    float lsum = 0.f;
    for (int kk = tid; kk < S_; kk += 128) {
        float e = (kk < len) ? __expf(sp[kk] - gmax) : 0.f;
        sp[kk] = e;
        lsum += e;
    }
    float gsum = block_sum(lsum, sred);
    float inv = 1.f / gsum;
    __syncthreads();

    // pass 3: P @ V  — two threads per output dim split the kk range
    int d = tid & 63, part = tid >> 6;
    float acc = 0.f;
    for (int kk = part; kk < len; kk += 2)
        acc = fmaf(sp[kk], g_v[((size_t)(b * S_ + kk) * H_ + hd) * DH_ + d], acc);
    so[tid] = acc;
    __syncthreads();
    if (tid < 64)
        g_o[(size_t)(b * S_ + qi) * D_ + hd * DH_ + d] = (so[tid] + so[tid + 64]) * inv;
}

// ---------------- fused residual + layernorm (in-place on g_h) ----------------
__global__ __launch_bounds__(256) void ln_residual_kernel(
    const float* __restrict__ res, const float* __restrict__ gma,
    const float* __restrict__ bta)
{
    int t = blockIdx.x;
    int tid = threadIdx.x;
    __shared__ float sred[32];

    float vals[3];
    float s = 0.f;
    #pragma unroll
    for (int i = 0; i < 3; i++) {
        int d = tid + i * 256;
        float v = g_h[(size_t)t * D_ + d] + res[(size_t)t * D_ + d];
        vals[i] = v;
        s += v;
    }
    float mean = block_sum(s, sred) * (1.f / D_);

    float sq = 0.f;
    #pragma unroll
    for (int i = 0; i < 3; i++) {
        float c = vals[i] - mean;
        sq += c * c;
    }
    float var = block_sum(sq, sred) * (1.f / D_);
    float invstd = rsqrtf(var + EPS_);

    #pragma unroll
    for (int i = 0; i < 3; i++) {
        int d = tid + i * 256;
        g_h[(size_t)t * D_ + d] = (vals[i] - mean) * invstd * gma[d] + bta[d];
    }
}

// ---------------- pooling + output projection ---------------------------------
__global__ __launch_bounds__(256) void pool_kernel(
    const int* __restrict__ lens, const float* __restrict__ out_w,
    const float* __restrict__ out_b, float* __restrict__ out)
{
    int b = blockIdx.x;
    int tid = threadIdx.x;
    int len = lens[b];
    __shared__ float sred[32];

    float acc = 0.f;
    float invlen = 1.f / (float)len;
    #pragma unroll
    for (int i = 0; i < 3; i++) {
        int d = tid + i * 256;
        float s = 0.f;
        for (int si = 0; si < len; si++)
            s += g_h[(size_t)(b * S_ + si) * D_ + d];
        acc += (s * invlen) * out_w[d];
    }
    float tot = block_sum(acc, sred);
    if (tid == 0) out[b] = tot + out_b[0];
}

// ---------------- launch -------------------------------------------------------
extern "C" void kernel_launch(void* const* d_in, const int* in_sizes, int n_in,
                              void* d_out, int out_size)
{
    const float* x     = (const float*)d_in[0];
    const int*   lens  = (const int*)  d_in[1];
    const float* in_w  = (const float*)d_in[2];
    const float* in_b  = (const float*)d_in[3];
    const float* pos   = (const float*)d_in[4];
    const float* qw    = (const float*)d_in[5];
    const float* qb    = (const float*)d_in[6];
    const float* kw    = (const float*)d_in[7];
    const float* kb    = (const float*)d_in[8];
    const float* vw    = (const float*)d_in[9];
    const float* vb    = (const float*)d_in[10];
    const float* w1    = (const float*)d_in[11];
    const float* b1    = (const float*)d_in[12];
    const float* w2    = (const float*)d_in[13];
    const float* b2    = (const float*)d_in[14];
    const float* ln1g  = (const float*)d_in[15];
    const float* ln1b  = (const float*)d_in[16];
    const float* ln2g  = (const float*)d_in[17];
    const float* ln2b  = (const float*)d_in[18];
    const float* out_w = (const float*)d_in[19];
    const float* out_b = (const float*)d_in[20];
    float* out = (float*)d_out;

    float *ph, *pq, *pk, *pv, *po, *pt, *pff;
    cudaGetSymbolAddress((void**)&ph,  g_h);
    cudaGetSymbolAddress((void**)&pq,  g_q);
    cudaGetSymbolAddress((void**)&pk,  g_k);
    cudaGetSymbolAddress((void**)&pv,  g_v);
    cudaGetSymbolAddress((void**)&po,  g_o);
    cudaGetSymbolAddress((void**)&pt,  g_t);
    cudaGetSymbolAddress((void**)&pff, g_ff);

    input_proj_kernel<<<MTOK, 256>>>(x, in_w, in_b, pos);

    dim3 gD  (D_   / 128, MTOK / 128);   // (6, 64)
    dim3 gDFF(DFF_ / 128, MTOK / 128);   // (24, 64)
    dim3 gAttn(S_, H_, B_);

    for (int l = 0; l < L_; l++) {
        const float* qwl = qw + (size_t)l * D_ * D_;
        const float* kwl = kw + (size_t)l * D_ * D_;
        const float* vwl = vw + (size_t)l * D_ * D_;
        const float* w1l = w1 + (size_t)l * D_ * DFF_;
        const float* w2l = w2 + (size_t)l * DFF_ * D_;

        gemm_kernel<<<gD, 256>>>(ph, qwl, qb + l * D_, pq, D_, D_, 0);
        gemm_kernel<<<gD, 256>>>(ph, kwl, kb + l * D_, pk, D_, D_, 0);
        gemm_kernel<<<gD, 256>>>(ph, vwl, vb + l * D_, pv, D_, D_, 0);

        attn_kernel<<<gAttn, 128>>>(lens);

        ln_residual_kernel<<<MTOK, 256>>>(po, ln1g + l * D_, ln1b + l * D_);

        gemm_kernel<<<gDFF, 256>>>(ph, w1l, b1 + l * DFF_, pff, DFF_, D_, 1);
        gemm_kernel<<<gD,   256>>>(pff, w2l, b2 + l * D_,  pt,  D_, DFF_, 0);

        ln_residual_kernel<<<MTOK, 256>>>(pt, ln2g + l * D_, ln2b + l * D_);
    }

    pool_kernel<<<B_, 256>>>(lens, out_w, out_b, out);
}

// round 3
// speedup vs baseline: 2.3435x; 2.3435x over previous
#include <cuda_runtime.h>
#include <math.h>
#include <stdint.h>

#define D_      768
#define DFF_    3072
#define S_      512
#define B_      16
#define H_      12
#define DH_     64
#define L_      6
#define MTOK    (B_ * S_)   // 8192
#define EPS_    1e-5f

// ---------------- scratch (device globals; no allocation allowed) -------------
__device__ float g_h [MTOK * D_];
__device__ float g_q [MTOK * D_];
__device__ float g_k [MTOK * D_];
__device__ float g_v [MTOK * D_];
__device__ float g_o [MTOK * D_];
__device__ float g_t [MTOK * D_];
__device__ float g_ff[MTOK * DFF_];
// transposed weights Wt[N,K] fp32 (pre-rounded to tf32)
__device__ float g_qwT[L_ * D_ * D_];
__device__ float g_kwT[L_ * D_ * D_];
__device__ float g_vwT[L_ * D_ * D_];
__device__ float g_w1T[L_ * D_ * DFF_];
__device__ float g_w2T[L_ * DFF_ * D_];

// ======================= helpers ==============================================
__device__ __forceinline__ uint32_t smem_u32(const void* p) {
    uint32_t a;
    asm("{ .reg .u64 t; cvta.to.shared.u64 t, %1; cvt.u32.u64 %0, t; }" : "=r"(a) : "l"(p));
    return a;
}
__device__ __forceinline__ void cp16(uint32_t saddr, const void* g) {
    asm volatile("cp.async.cg.shared.global [%0], [%1], 16;" :: "r"(saddr), "l"(g));
}
#define CP_COMMIT()  asm volatile("cp.async.commit_group;" ::: "memory")
#define CP_WAIT1()   asm volatile("cp.async.wait_group 1;" ::: "memory")
#define CP_WAIT0()   asm volatile("cp.async.wait_group 0;" ::: "memory")

__device__ __forceinline__ uint32_t f2tf32(float x) {
    uint32_t u;
    asm("cvt.rna.tf32.f32 %0, %1;" : "=r"(u) : "f"(x));
    return u;
}
__device__ __forceinline__ void mma_tf32(
    float& c0, float& c1, float& c2, float& c3,
    uint32_t a0, uint32_t a1, uint32_t a2, uint32_t a3,
    uint32_t b0, uint32_t b1)
{
    asm volatile(
        "mma.sync.aligned.m16n8k8.row.col.f32.tf32.tf32.f32 "
        "{%0,%1,%2,%3}, {%4,%5,%6,%7}, {%8,%9}, {%0,%1,%2,%3};"
        : "+f"(c0), "+f"(c1), "+f"(c2), "+f"(c3)
        : "r"(a0), "r"(a1), "r"(a2), "r"(a3), "r"(b0), "r"(b1));
}

// ---------------- GEMM config --------------------------------------------------
#define BM      128
#define BN      128
#define BK      32
#define NSTG    3
#define PAD     36                          // floats per smem row (bank-conflict-free)
#define STG_F   (128 * PAD)                 // floats per tile per stage
#define SMEM_GEMM (2 * NSTG * STG_F * 4)    // 110592 bytes

// ============ tf32 mma.sync GEMM: C[M,N] = A[M,K] @ Wt[N,K]^T + bias ==========
__global__ __launch_bounds__(256) void gemm_mma(
    const float* __restrict__ A, const float* __restrict__ Wt,
    const float* __restrict__ bias, float* __restrict__ C,
    int N, int K, int relu)
{
    extern __shared__ float smem[];
    float* As = smem;
    float* Bs = smem + NSTG * STG_F;
    uint32_t sA = smem_u32(As);
    uint32_t sB = smem_u32(Bs);

    int tid  = threadIdx.x;
    int lane = tid & 31;
    int wid  = tid >> 5;
    int grp  = lane >> 2, tg = lane & 3;
    int bm = blockIdx.y * BM;
    int bn = blockIdx.x * BN;
    int m0 = (wid & 1) * 64;     // warp M offset within tile
    int n0 = (wid >> 1) * 32;    // warp N offset within tile

    float acc[4][4][4];
    #pragma unroll
    for (int i = 0; i < 4; i++)
        #pragma unroll
        for (int j = 0; j < 4; j++)
            #pragma unroll
            for (int q = 0; q < 4; q++) acc[i][j][q] = 0.f;

    const int nk = K / BK;

    #define LOAD_STAGE(s, k0) do {                                              \
        _Pragma("unroll")                                                       \
        for (int i = 0; i < 4; i++) {                                           \
            int ch = tid + i * 256;          /* 0..1023 */                      \
            int row = ch >> 3, kc = (ch & 7) * 4;                               \
            uint32_t off = (uint32_t)(((s) * STG_F + row * PAD + kc) * 4);      \
            cp16(sA + off, A  + (size_t)(bm + row) * K + (k0) + kc);            \
            cp16(sB + off, Wt + (size_t)(bn + row) * K + (k0) + kc);            \
        }                                                                       \
        CP_COMMIT();                                                            \
    } while (0)

    LOAD_STAGE(0, 0);
    LOAD_STAGE(1, BK);

    for (int step = 0; step < nk; step++) {
        int cur = step % NSTG;
        if (step + 2 <= nk) { CP_WAIT1(); } else { CP_WAIT0(); }
        __syncthreads();

        int nxt = step + 2;
        if (nxt < nk) LOAD_STAGE(nxt % NSTG, nxt * BK);

        const float* Ac = As + cur * STG_F;
        const float* Bc = Bs + cur * STG_F;

        #pragma unroll
        for (int kk = 0; kk < 4; kk++) {          // four k8 sub-steps
            int kb = kk * 8;
            uint32_t af[4][4];
            #pragma unroll
            for (int im = 0; im < 4; im++) {
                const float* ap = Ac + (m0 + im * 16 + grp) * PAD + kb + tg;
                af[im][0] = f2tf32(ap[0]);
                af[im][1] = f2tf32(ap[8 * PAD]);
                af[im][2] = f2tf32(ap[4]);
                af[im][3] = f2tf32(ap[8 * PAD + 4]);
            }
            uint32_t bf[4][2];
            #pragma unroll
            for (int in_ = 0; in_ < 4; in_++) {
                const float* bp = Bc + (n0 + in_ * 8 + grp) * PAD + kb + tg;
                bf[in_][0] = __float_as_uint(bp[0]);
                bf[in_][1] = __float_as_uint(bp[4]);
            }
            #pragma unroll
            for (int im = 0; im < 4; im++)
                #pragma unroll
                for (int in_ = 0; in_ < 4; in_++)
                    mma_tf32(acc[im][in_][0], acc[im][in_][1],
                             acc[im][in_][2], acc[im][in_][3],
                             af[im][0], af[im][1], af[im][2], af[im][3],
                             bf[in_][0], bf[in_][1]);
        }
        __syncthreads();
    }

    // epilogue: c0,c1 at (row, col..col+1), c2,c3 at (row+8, ...)
    #pragma unroll
    for (int im = 0; im < 4; im++) {
        int row = bm + m0 + im * 16 + grp;
        #pragma unroll
        for (int in_ = 0; in_ < 4; in_++) {
            int col = bn + n0 + in_ * 8 + tg * 2;
            float2 bv = *(const float2*)&bias[col];
            float2 v0, v1;
            v0.x = acc[im][in_][0] + bv.x;
            v0.y = acc[im][in_][1] + bv.y;
            v1.x = acc[im][in_][2] + bv.x;
            v1.y = acc[im][in_][3] + bv.y;
            if (relu) {
                v0.x = fmaxf(v0.x, 0.f); v0.y = fmaxf(v0.y, 0.f);
                v1.x = fmaxf(v1.x, 0.f); v1.y = fmaxf(v1.y, 0.f);
            }
            *(float2*)&C[(size_t)row * N + col]       = v0;
            *(float2*)&C[(size_t)(row + 8) * N + col] = v1;
        }
    }
    #undef LOAD_STAGE
}

// ---------------- weight transpose (+ tf32 rounding) ---------------------------
__global__ __launch_bounds__(256) void transpose_kernel(
    const float* __restrict__ src, float* __restrict__ dst, int R, int C)
{
    __shared__ float t[32][33];
    src += (size_t)blockIdx.z * R * C;
    dst += (size_t)blockIdx.z * R * C;
    int c0 = blockIdx.x * 32, r0 = blockIdx.y * 32;
    int x = threadIdx.x & 31, y = threadIdx.x >> 5;   // 32 x 8
    #pragma unroll
    for (int i = 0; i < 32; i += 8)
        t[y + i][x] = src[(size_t)(r0 + y + i) * C + c0 + x];
    __syncthreads();
    #pragma unroll
    for (int i = 0; i < 32; i += 8)
        dst[(size_t)(c0 + y + i) * R + r0 + x] = __uint_as_float(f2tf32(t[x][y + i]));
}

// ---------------- block reductions ---------------------------------------------
__device__ __forceinline__ float block_sum(float v, float* sred) {
    #pragma unroll
    for (int o = 16; o > 0; o >>= 1) v += __shfl_xor_sync(0xffffffffu, v, o);
    int wid = threadIdx.x >> 5, lid = threadIdx.x & 31;
    int nw = (blockDim.x + 31) >> 5;
    __syncthreads();
    if (lid == 0) sred[wid] = v;
    __syncthreads();
    if (wid == 0) {
        float t = (lid < nw) ? sred[lid] : 0.f;
        #pragma unroll
        for (int o = 16; o > 0; o >>= 1) t += __shfl_xor_sync(0xffffffffu, t, o);
        if (lid == 0) sred[0] = t;
    }
    __syncthreads();
    return sred[0];
}
__device__ __forceinline__ float block_max(float v, float* sred) {
    #pragma unroll
    for (int o = 16; o > 0; o >>= 1) v = fmaxf(v, __shfl_xor_sync(0xffffffffu, v, o));
    int wid = threadIdx.x >> 5, lid = threadIdx.x & 31;
    int nw = (blockDim.x + 31) >> 5;
    __syncthreads();
    if (lid == 0) sred[wid] = v;
    __syncthreads();
    if (wid == 0) {
        float t = (lid < nw) ? sred[lid] : -INFINITY;
        #pragma unroll
        for (int o = 16; o > 0; o >>= 1) t = fmaxf(t, __shfl_xor_sync(0xffffffffu, t, o));
        if (lid == 0) sred[0] = t;
    }
    __syncthreads();
    return sred[0];
}

// ---------------- input projection ---------------------------------------------
__global__ __launch_bounds__(256) void input_proj_kernel(
    const float* __restrict__ x, const float* __restrict__ in_w,
    const float* __restrict__ in_b, const float* __restrict__ pos)
{
    int t = blockIdx.x;
    int s = t & (S_ - 1);
    __shared__ float sx[32];
    if (threadIdx.x < 32) sx[threadIdx.x] = x[t * 32 + threadIdx.x];
    __syncthreads();
    for (int d = threadIdx.x; d < D_; d += 256) {
        float acc = in_b[d] + pos[s * D_ + d];
        #pragma unroll
        for (int kk = 0; kk < 32; kk++) acc = fmaf(sx[kk], in_w[kk * D_ + d], acc);
        g_h[t * D_ + d] = acc;
    }
}

// ---------------- attention (early-exit dead q rows) ----------------------------
__global__ __launch_bounds__(128) void attn_kernel(const int* __restrict__ lens)
{
    int qi = blockIdx.x, hd = blockIdx.y, b = blockIdx.z;
    int len = lens[b];
    if (qi >= len) return;   // dead row: never influences any valid output
    int tid = threadIdx.x;

    __shared__ float sq[DH_];
    __shared__ float sp[S_];
    __shared__ float sred[32];
    __shared__ float so[128];

    const float* qrow = g_q + ((size_t)(b * S_ + qi) * H_ + hd) * DH_;
    if (tid < DH_) sq[tid] = qrow[tid];
    __syncthreads();

    float lmax = -INFINITY;
    for (int kk = tid; kk < S_; kk += 128) {
        float sc;
        if (kk < len) {
            const float4* kr = (const float4*)(g_k + ((size_t)(b * S_ + kk) * H_ + hd) * DH_);
            float acc = 0.f;
            #pragma unroll
            for (int j = 0; j < 16; j++) {
                float4 kv = kr[j];
                float4 qv = *(const float4*)&sq[j * 4];
                acc += kv.x * qv.x + kv.y * qv.y + kv.z * qv.z + kv.w * qv.w;
            }
            sc = acc * 0.125f;
        } else {
            sc = -INFINITY;
        }
        sp[kk] = sc;
        lmax = fmaxf(lmax, sc);
    }
    float gmax = block_max(lmax, sred);

    float lsum = 0.f;
    for (int kk = tid; kk < S_; kk += 128) {
        float e = (kk < len) ? __expf(sp[kk] - gmax) : 0.f;
        sp[kk] = e;
        lsum += e;
    }
    float gsum = block_sum(lsum, sred);
    float inv = 1.f / gsum;
    __syncthreads();

    int d = tid & 63, part = tid >> 6;
    float acc = 0.f;
    for (int kk = part; kk < len; kk += 2)
        acc = fmaf(sp[kk], g_v[((size_t)(b * S_ + kk) * H_ + hd) * DH_ + d], acc);
    so[tid] = acc;
    __syncthreads();
    if (tid < 64)
        g_o[(size_t)(b * S_ + qi) * D_ + hd * DH_ + d] = (so[tid] + so[tid + 64]) * inv;
}

// ---------------- fused residual + layernorm ------------------------------------
__global__ __launch_bounds__(256) void ln_residual_kernel(
    const float* __restrict__ res, const float* __restrict__ gma,
    const float* __restrict__ bta)
{
    int t = blockIdx.x;
    int tid = threadIdx.x;
    __shared__ float sred[32];

    float vals[3];
    float s = 0.f;
    #pragma unroll
    for (int i = 0; i < 3; i++) {
        int d = tid + i * 256;
        float v = g_h[(size_t)t * D_ + d] + res[(size_t)t * D_ + d];
        vals[i] = v;
        s += v;
    }
    float mean = block_sum(s, sred) * (1.f / D_);

    float sq = 0.f;
    #pragma unroll
    for (int i = 0; i < 3; i++) { float c = vals[i] - mean; sq += c * c; }
    float var = block_sum(sq, sred) * (1.f / D_);
    float invstd = rsqrtf(var + EPS_);

    #pragma unroll
    for (int i = 0; i < 3; i++) {
        int d = tid + i * 256;
        g_h[(size_t)t * D_ + d] = (vals[i] - mean) * invstd * gma[d] + bta[d];
    }
}

// ---------------- pooling + output projection -----------------------------------
__global__ __launch_bounds__(256) void pool_kernel(
    const int* __restrict__ lens, const float* __restrict__ out_w,
    const float* __restrict__ out_b, float* __restrict__ out)
{
    int b = blockIdx.x;
    int tid = threadIdx.x;
    int len = lens[b];
    __shared__ float sred[32];

    float acc = 0.f;
    float invlen = 1.f / (float)len;
    #pragma unroll
    for (int i = 0; i < 3; i++) {
        int d = tid + i * 256;
        float s = 0.f;
        for (int si = 0; si < len; si++)
            s += g_h[(size_t)(b * S_ + si) * D_ + d];
        acc += (s * invlen) * out_w[d];
    }
    float tot = block_sum(acc, sred);
    if (tid == 0) out[b] = tot + out_b[0];
}

// ---------------- launch ---------------------------------------------------------
extern "C" void kernel_launch(void* const* d_in, const int* in_sizes, int n_in,
                              void* d_out, int out_size)
{
    const float* x     = (const float*)d_in[0];
    const int*   lens  = (const int*)  d_in[1];
    const float* in_w  = (const float*)d_in[2];
    const float* in_b  = (const float*)d_in[3];
    const float* pos   = (const float*)d_in[4];
    const float* qw    = (const float*)d_in[5];
    const float* qb    = (const float*)d_in[6];
    const float* kw    = (const float*)d_in[7];
    const float* kb    = (const float*)d_in[8];
    const float* vw    = (const float*)d_in[9];
    const float* vb    = (const float*)d_in[10];
    const float* w1    = (const float*)d_in[11];
    const float* b1    = (const float*)d_in[12];
    const float* w2    = (const float*)d_in[13];
    const float* b2    = (const float*)d_in[14];
    const float* ln1g  = (const float*)d_in[15];
    const float* ln1b  = (const float*)d_in[16];
    const float* ln2g  = (const float*)d_in[17];
    const float* ln2b  = (const float*)d_in[18];
    const float* out_w = (const float*)d_in[19];
    const float* out_b = (const float*)d_in[20];
    float* out = (float*)d_out;

    float *ph, *pq, *pk, *pv, *po, *pt, *pff;
    float *pqwT, *pkwT, *pvwT, *pw1T, *pw2T;
    cudaGetSymbolAddress((void**)&ph,  g_h);
    cudaGetSymbolAddress((void**)&pq,  g_q);
    cudaGetSymbolAddress((void**)&pk,  g_k);
    cudaGetSymbolAddress((void**)&pv,  g_v);
    cudaGetSymbolAddress((void**)&po,  g_o);
    cudaGetSymbolAddress((void**)&pt,  g_t);
    cudaGetSymbolAddress((void**)&pff, g_ff);
    cudaGetSymbolAddress((void**)&pqwT, g_qwT);
    cudaGetSymbolAddress((void**)&pkwT, g_kwT);
    cudaGetSymbolAddress((void**)&pvwT, g_vwT);
    cudaGetSymbolAddress((void**)&pw1T, g_w1T);
    cudaGetSymbolAddress((void**)&pw2T, g_w2T);

    cudaFuncSetAttribute(gemm_mma, cudaFuncAttributeMaxDynamicSharedMemorySize, SMEM_GEMM);

    // weight transposes: Wt[N,K] = W[K,N]^T, rounded to tf32
    transpose_kernel<<<dim3(24, 24, L_), 256>>>(qw, pqwT, D_, D_);
    transpose_kernel<<<dim3(24, 24, L_), 256>>>(kw, pkwT, D_, D_);
    transpose_kernel<<<dim3(24, 24, L_), 256>>>(vw, pvwT, D_, D_);
    transpose_kernel<<<dim3(96, 24, L_), 256>>>(w1, pw1T, D_, DFF_);
    transpose_kernel<<<dim3(24, 96, L_), 256>>>(w2, pw2T, DFF_, D_);

    input_proj_kernel<<<MTOK, 256>>>(x, in_w, in_b, pos);

    dim3 gD  (D_   / 128, MTOK / 128);   // (6, 64)
    dim3 gDFF(DFF_ / 128, MTOK / 128);   // (24, 64)
    dim3 gAttn(S_, H_, B_);

    for (int l = 0; l < L_; l++) {
        const float* qwTl = pqwT + (size_t)l * D_ * D_;
        const float* kwTl = pkwT + (size_t)l * D_ * D_;
        const float* vwTl = pvwT + (size_t)l * D_ * D_;
        const float* w1Tl = pw1T + (size_t)l * D_ * DFF_;
        const float* w2Tl = pw2T + (size_t)l * DFF_ * D_;

        gemm_mma<<<gD, 256, SMEM_GEMM>>>(ph, qwTl, qb + l * D_, pq, D_, D_, 0);
        gemm_mma<<<gD, 256, SMEM_GEMM>>>(ph, kwTl, kb + l * D_, pk, D_, D_, 0);
        gemm_mma<<<gD, 256, SMEM_GEMM>>>(ph, vwTl, vb + l * D_, pv, D_, D_, 0);

        attn_kernel<<<gAttn, 128>>>(lens);

        ln_residual_kernel<<<MTOK, 256>>>(po, ln1g + l * D_, ln1b + l * D_);

        gemm_mma<<<gDFF, 256, SMEM_GEMM>>>(ph, w1Tl, b1 + l * DFF_, pff, DFF_, D_, 1);
        gemm_mma<<<gD,   256, SMEM_GEMM>>>(pff, w2Tl, b2 + l * D_,  pt,  D_, DFF_, 0);

        ln_residual_kernel<<<MTOK, 256>>>(pt, ln2g + l * D_, ln2b + l * D_);
    }

    pool_kernel<<<B_, 256>>>(lens, out_w, out_b, out);
}

// round 4
// speedup vs baseline: 2.4859x; 1.0607x over previous
#include <cuda_runtime.h>
#include <math.h>
#include <stdint.h>

#define D_      768
#define DFF_    3072
#define S_      512
#define B_      16
#define H_      12
#define DH_     64
#define L_      6
#define MTOK    (B_ * S_)   // 8192
#define EPS_    1e-5f

// ---------------- scratch (device globals; no allocation allowed) -------------
__device__ float g_h [MTOK * D_];
__device__ float g_q [MTOK * D_];
__device__ float g_k [MTOK * D_];
__device__ float g_v [MTOK * D_];
__device__ float g_o [MTOK * D_];
__device__ float g_t [MTOK * D_];
__device__ float g_ff[MTOK * DFF_];
// transposed weights Wt[N,K] fp32 (pre-rounded to tf32)
__device__ float g_qwT[L_ * D_ * D_];
__device__ float g_kwT[L_ * D_ * D_];
__device__ float g_vwT[L_ * D_ * D_];
__device__ float g_w1T[L_ * D_ * DFF_];
__device__ float g_w2T[L_ * DFF_ * D_];

// ======================= helpers ==============================================
__device__ __forceinline__ uint32_t smem_u32(const void* p) {
    uint32_t a;
    asm("{ .reg .u64 t; cvta.to.shared.u64 t, %1; cvt.u32.u64 %0, t; }" : "=r"(a) : "l"(p));
    return a;
}
__device__ __forceinline__ void cp16(uint32_t saddr, const void* g) {
    asm volatile("cp.async.cg.shared.global [%0], [%1], 16;" :: "r"(saddr), "l"(g));
}
#define CP_COMMIT()  asm volatile("cp.async.commit_group;" ::: "memory")
#define CP_WAIT1()   asm volatile("cp.async.wait_group 1;" ::: "memory")
#define CP_WAIT0()   asm volatile("cp.async.wait_group 0;" ::: "memory")

__device__ __forceinline__ uint32_t f2tf32(float x) {
    uint32_t u;
    asm("cvt.rna.tf32.f32 %0, %1;" : "=r"(u) : "f"(x));
    return u;
}
__device__ __forceinline__ void ldm_x4(uint32_t& r0, uint32_t& r1, uint32_t& r2,
                                       uint32_t& r3, uint32_t addr) {
    asm volatile("ldmatrix.sync.aligned.m8n8.x4.shared.b16 {%0,%1,%2,%3}, [%4];"
                 : "=r"(r0), "=r"(r1), "=r"(r2), "=r"(r3) : "r"(addr));
}
__device__ __forceinline__ void mma_tf32(
    float& c0, float& c1, float& c2, float& c3,
    uint32_t a0, uint32_t a1, uint32_t a2, uint32_t a3,
    uint32_t b0, uint32_t b1)
{
    asm volatile(
        "mma.sync.aligned.m16n8k8.row.col.f32.tf32.tf32.f32 "
        "{%0,%1,%2,%3}, {%4,%5,%6,%7}, {%8,%9}, {%0,%1,%2,%3};"
        : "+f"(c0), "+f"(c1), "+f"(c2), "+f"(c3)
        : "r"(a0), "r"(a1), "r"(a2), "r"(a3), "r"(b0), "r"(b1));
}

// ---------------- GEMM config --------------------------------------------------
#define BM      128
#define BN      128
#define BK      32
#define NSTG    3
#define PAD     36                          // floats per smem row (bank-conflict-free)
#define STG_F   (128 * PAD)                 // floats per tile per stage
#define SMEM_GEMM (2 * NSTG * STG_F * 4)    // 110592 bytes

// ============ tf32 mma.sync GEMM: C[M,N] = A[M,K] @ Wt[N,K]^T + bias ==========
__global__ __launch_bounds__(256) void gemm_mma(
    const float* __restrict__ A, const float* __restrict__ Wt,
    const float* __restrict__ bias, float* __restrict__ C,
    int N, int K, int relu)
{
    extern __shared__ float smem[];
    float* As = smem;
    float* Bs = smem + NSTG * STG_F;
    uint32_t sA = smem_u32(As);
    uint32_t sB = smem_u32(Bs);

    int tid  = threadIdx.x;
    int lane = tid & 31;
    int wid  = tid >> 5;
    int grp  = lane >> 2, tg = lane & 3;
    int bm = blockIdx.y * BM;
    int bn = blockIdx.x * BN;
    int m0 = (wid & 1) * 64;     // warp M offset within tile
    int n0 = (wid >> 1) * 32;    // warp N offset within tile

    // ldmatrix lane-address components (byte offsets into a stage's tile)
    // A x4: mats = {rows m..m+7 cols kb..kb+3, rows m+8.. cols kb..+3,
    //               rows m..m+7 cols kb+4..+7, rows m+8.. cols kb+4..+7}
    uint32_t a_lane = ((((lane >> 3) & 1) * 8 + (lane & 7)) * PAD
                       + ((lane >> 4) & 1) * 4) * 4;
    // B x4 covers two n8 tiles: lanes 0-15 tile n.., lanes 16-31 tile n+8
    uint32_t b_lane = ((((lane >> 4) & 1) * 8 + (lane & 7)) * PAD
                       + ((lane >> 3) & 1) * 4) * 4;
    uint32_t aw = sA + (uint32_t)(m0 * PAD) * 4 + a_lane;
    uint32_t bw = sB + (uint32_t)(n0 * PAD) * 4 + b_lane;

    float acc[4][4][4];
    #pragma unroll
    for (int i = 0; i < 4; i++)
        #pragma unroll
        for (int j = 0; j < 4; j++)
            #pragma unroll
            for (int q = 0; q < 4; q++) acc[i][j][q] = 0.f;

    const int nk = K / BK;

    #define LOAD_STAGE(s, k0) do {                                              \
        _Pragma("unroll")                                                       \
        for (int i = 0; i < 4; i++) {                                           \
            int ch = tid + i * 256;          /* 0..1023 */                      \
            int row = ch >> 3, kc = (ch & 7) * 4;                               \
            uint32_t off = (uint32_t)(((s) * STG_F + row * PAD + kc) * 4);      \
            cp16(sA + off, A  + (size_t)(bm + row) * K + (k0) + kc);            \
            cp16(sB + off, Wt + (size_t)(bn + row) * K + (k0) + kc);            \
        }                                                                       \
        CP_COMMIT();                                                            \
    } while (0)

    LOAD_STAGE(0, 0);
    LOAD_STAGE(1, BK);

    for (int step = 0; step < nk; step++) {
        int cur = step % NSTG;
        if (step + 2 <= nk) { CP_WAIT1(); } else { CP_WAIT0(); }
        __syncthreads();

        int nxt = step + 2;
        if (nxt < nk) LOAD_STAGE(nxt % NSTG, nxt * BK);

        uint32_t abase = aw + (uint32_t)(cur * STG_F) * 4;
        uint32_t bbase = bw + (uint32_t)(cur * STG_F) * 4;

        #pragma unroll
        for (int kk = 0; kk < 4; kk++) {          // four k8 sub-steps
            uint32_t kboff = (uint32_t)kk * 32;   // 8 floats = 32 bytes
            uint32_t af[4][4];
            #pragma unroll
            for (int im = 0; im < 4; im++)
                ldm_x4(af[im][0], af[im][1], af[im][2], af[im][3],
                       abase + (uint32_t)(im * 16 * PAD) * 4 + kboff);
            uint32_t bf[4][2];
            ldm_x4(bf[0][0], bf[0][1], bf[1][0], bf[1][1], bbase + kboff);
            ldm_x4(bf[2][0], bf[2][1], bf[3][0], bf[3][1],
                   bbase + (uint32_t)(16 * PAD) * 4 + kboff);
            #pragma unroll
            for (int im = 0; im < 4; im++)
                #pragma unroll
                for (int in_ = 0; in_ < 4; in_++)
                    mma_tf32(acc[im][in_][0], acc[im][in_][1],
                             acc[im][in_][2], acc[im][in_][3],
                             af[im][0], af[im][1], af[im][2], af[im][3],
                             bf[in_][0], bf[in_][1]);
        }
        __syncthreads();
    }

    // epilogue: c0,c1 at (row, col..col+1), c2,c3 at (row+8, ...)
    #pragma unroll
    for (int im = 0; im < 4; im++) {
        int row = bm + m0 + im * 16 + grp;
        #pragma unroll
        for (int in_ = 0; in_ < 4; in_++) {
            int col = bn + n0 + in_ * 8 + tg * 2;
            float2 bv = *(const float2*)&bias[col];
            float2 v0, v1;
            v0.x = acc[im][in_][0] + bv.x;
            v0.y = acc[im][in_][1] + bv.y;
            v1.x = acc[im][in_][2] + bv.x;
            v1.y = acc[im][in_][3] + bv.y;
            if (relu) {
                v0.x = fmaxf(v0.x, 0.f); v0.y = fmaxf(v0.y, 0.f);
                v1.x = fmaxf(v1.x, 0.f); v1.y = fmaxf(v1.y, 0.f);
            }
            *(float2*)&C[(size_t)row * N + col]       = v0;
            *(float2*)&C[(size_t)(row + 8) * N + col] = v1;
        }
    }
    #undef LOAD_STAGE
}

// ---------------- weight transpose (+ tf32 rounding) ---------------------------
__global__ __launch_bounds__(256) void transpose_kernel(
    const float* __restrict__ src, float* __restrict__ dst, int R, int C)
{
    __shared__ float t[32][33];
    src += (size_t)blockIdx.z * R * C;
    dst += (size_t)blockIdx.z * R * C;
    int c0 = blockIdx.x * 32, r0 = blockIdx.y * 32;
    int x = threadIdx.x & 31, y = threadIdx.x >> 5;   // 32 x 8
    #pragma unroll
    for (int i = 0; i < 32; i += 8)
        t[y + i][x] = src[(size_t)(r0 + y + i) * C + c0 + x];
    __syncthreads();
    #pragma unroll
    for (int i = 0; i < 32; i += 8)
        dst[(size_t)(c0 + y + i) * R + r0 + x] = __uint_as_float(f2tf32(t[x][y + i]));
}

// ---------------- block reductions ---------------------------------------------
__device__ __forceinline__ float block_sum(float v, float* sred) {
    #pragma unroll
    for (int o = 16; o > 0; o >>= 1) v += __shfl_xor_sync(0xffffffffu, v, o);
    int wid = threadIdx.x >> 5, lid = threadIdx.x & 31;
    int nw = (blockDim.x + 31) >> 5;
    __syncthreads();
    if (lid == 0) sred[wid] = v;
    __syncthreads();
    if (wid == 0) {
        float t = (lid < nw) ? sred[lid] : 0.f;
        #pragma unroll
        for (int o = 16; o > 0; o >>= 1) t += __shfl_xor_sync(0xffffffffu, t, o);
        if (lid == 0) sred[0] = t;
    }
    __syncthreads();
    return sred[0];
}
__device__ __forceinline__ float block_max(float v, float* sred) {
    #pragma unroll
    for (int o = 16; o > 0; o >>= 1) v = fmaxf(v, __shfl_xor_sync(0xffffffffu, v, o));
    int wid = threadIdx.x >> 5, lid = threadIdx.x & 31;
    int nw = (blockDim.x + 31) >> 5;
    __syncthreads();
    if (lid == 0) sred[wid] = v;
    __syncthreads();
    if (wid == 0) {
        float t = (lid < nw) ? sred[lid] : -INFINITY;
        #pragma unroll
        for (int o = 16; o > 0; o >>= 1) t = fmaxf(t, __shfl_xor_sync(0xffffffffu, t, o));
        if (lid == 0) sred[0] = t;
    }
    __syncthreads();
    return sred[0];
}

// ---------------- input projection ---------------------------------------------
__global__ __launch_bounds__(256) void input_proj_kernel(
    const float* __restrict__ x, const float* __restrict__ in_w,
    const float* __restrict__ in_b, const float* __restrict__ pos)
{
    int t = blockIdx.x;
    int s = t & (S_ - 1);
    __shared__ float sx[32];
    if (threadIdx.x < 32) sx[threadIdx.x] = x[t * 32 + threadIdx.x];
    __syncthreads();
    for (int d = threadIdx.x; d < D_; d += 256) {
        float acc = in_b[d] + pos[s * D_ + d];
        #pragma unroll
        for (int kk = 0; kk < 32; kk++) acc = fmaf(sx[kk], in_w[kk * D_ + d], acc);
        g_h[t * D_ + d] = acc;
    }
}

// ---------------- attention (early-exit dead q rows) ----------------------------
__global__ __launch_bounds__(128) void attn_kernel(const int* __restrict__ lens)
{
    int qi = blockIdx.x, hd = blockIdx.y, b = blockIdx.z;
    int len = lens[b];
    if (qi >= len) return;   // dead row: never influences any valid output
    int tid = threadIdx.x;

    __shared__ float sq[DH_];
    __shared__ float sp[S_];
    __shared__ float sred[32];
    __shared__ float so[128];

    const float* qrow = g_q + ((size_t)(b * S_ + qi) * H_ + hd) * DH_;
    if (tid < DH_) sq[tid] = qrow[tid];
    __syncthreads();

    float lmax = -INFINITY;
    for (int kk = tid; kk < S_; kk += 128) {
        float sc;
        if (kk < len) {
            const float4* kr = (const float4*)(g_k + ((size_t)(b * S_ + kk) * H_ + hd) * DH_);
            float acc = 0.f;
            #pragma unroll
            for (int j = 0; j < 16; j++) {
                float4 kv = kr[j];
                float4 qv = *(const float4*)&sq[j * 4];
                acc += kv.x * qv.x + kv.y * qv.y + kv.z * qv.z + kv.w * qv.w;
            }
            sc = acc * 0.125f;
        } else {
            sc = -INFINITY;
        }
        sp[kk] = sc;
        lmax = fmaxf(lmax, sc);
    }
    float gmax = block_max(lmax, sred);

    float lsum = 0.f;
    for (int kk = tid; kk < S_; kk += 128) {
        float e = (kk < len) ? __expf(sp[kk] - gmax) : 0.f;
        sp[kk] = e;
        lsum += e;
    }
    float gsum = block_sum(lsum, sred);
    float inv = 1.f / gsum;
    __syncthreads();

    int d = tid & 63, part = tid >> 6;
    float acc = 0.f;
    for (int kk = part; kk < len; kk += 2)
        acc = fmaf(sp[kk], g_v[((size_t)(b * S_ + kk) * H_ + hd) * DH_ + d], acc);
    so[tid] = acc;
    __syncthreads();
    if (tid < 64)
        g_o[(size_t)(b * S_ + qi) * D_ + hd * DH_ + d] = (so[tid] + so[tid + 64]) * inv;
}

// ---------------- fused residual + layernorm ------------------------------------
__global__ __launch_bounds__(256) void ln_residual_kernel(
    const float* __restrict__ res, const float* __restrict__ gma,
    const float* __restrict__ bta)
{
    int t = blockIdx.x;
    int tid = threadIdx.x;
    __shared__ float sred[32];

    float vals[3];
    float s = 0.f;
    #pragma unroll
    for (int i = 0; i < 3; i++) {
        int d = tid + i * 256;
        float v = g_h[(size_t)t * D_ + d] + res[(size_t)t * D_ + d];
        vals[i] = v;
        s += v;
    }
    float mean = block_sum(s, sred) * (1.f / D_);

    float sq = 0.f;
    #pragma unroll
    for (int i = 0; i < 3; i++) { float c = vals[i] - mean; sq += c * c; }
    float var = block_sum(sq, sred) * (1.f / D_);
    float invstd = rsqrtf(var + EPS_);

    #pragma unroll
    for (int i = 0; i < 3; i++) {
        int d = tid + i * 256;
        g_h[(size_t)t * D_ + d] = (vals[i] - mean) * invstd * gma[d] + bta[d];
    }
}

// ---------------- pooling + output projection -----------------------------------
__global__ __launch_bounds__(256) void pool_kernel(
    const int* __restrict__ lens, const float* __restrict__ out_w,
    const float* __restrict__ out_b, float* __restrict__ out)
{
    int b = blockIdx.x;
    int tid = threadIdx.x;
    int len = lens[b];
    __shared__ float sred[32];

    float acc = 0.f;
    float invlen = 1.f / (float)len;
    #pragma unroll
    for (int i = 0; i < 3; i++) {
        int d = tid + i * 256;
        float s = 0.f;
        for (int si = 0; si < len; si++)
            s += g_h[(size_t)(b * S_ + si) * D_ + d];
        acc += (s * invlen) * out_w[d];
    }
    float tot = block_sum(acc, sred);
    if (tid == 0) out[b] = tot + out_b[0];
}

// ---------------- launch ---------------------------------------------------------
extern "C" void kernel_launch(void* const* d_in, const int* in_sizes, int n_in,
                              void* d_out, int out_size)
{
    const float* x     = (const float*)d_in[0];
    const int*   lens  = (const int*)  d_in[1];
    const float* in_w  = (const float*)d_in[2];
    const float* in_b  = (const float*)d_in[3];
    const float* pos   = (const float*)d_in[4];
    const float* qw    = (const float*)d_in[5];
    const float* qb    = (const float*)d_in[6];
    const float* kw    = (const float*)d_in[7];
    const float* kb    = (const float*)d_in[8];
    const float* vw    = (const float*)d_in[9];
    const float* vb    = (const float*)d_in[10];
    const float* w1    = (const float*)d_in[11];
    const float* b1    = (const float*)d_in[12];
    const float* w2    = (const float*)d_in[13];
    const float* b2    = (const float*)d_in[14];
    const float* ln1g  = (const float*)d_in[15];
    const float* ln1b  = (const float*)d_in[16];
    const float* ln2g  = (const float*)d_in[17];
    const float* ln2b  = (const float*)d_in[18];
    const float* out_w = (const float*)d_in[19];
    const float* out_b = (const float*)d_in[20];
    float* out = (float*)d_out;

    float *ph, *pq, *pk, *pv, *po, *pt, *pff;
    float *pqwT, *pkwT, *pvwT, *pw1T, *pw2T;
    cudaGetSymbolAddress((void**)&ph,  g_h);
    cudaGetSymbolAddress((void**)&pq,  g_q);
    cudaGetSymbolAddress((void**)&pk,  g_k);
    cudaGetSymbolAddress((void**)&pv,  g_v);
    cudaGetSymbolAddress((void**)&po,  g_o);
    cudaGetSymbolAddress((void**)&pt,  g_t);
    cudaGetSymbolAddress((void**)&pff, g_ff);
    cudaGetSymbolAddress((void**)&pqwT, g_qwT);
    cudaGetSymbolAddress((void**)&pkwT, g_kwT);
    cudaGetSymbolAddress((void**)&pvwT, g_vwT);
    cudaGetSymbolAddress((void**)&pw1T, g_w1T);
    cudaGetSymbolAddress((void**)&pw2T, g_w2T);

    cudaFuncSetAttribute(gemm_mma, cudaFuncAttributeMaxDynamicSharedMemorySize, SMEM_GEMM);

    // weight transposes: Wt[N,K] = W[K,N]^T, rounded to tf32
    transpose_kernel<<<dim3(24, 24, L_), 256>>>(qw, pqwT, D_, D_);
    transpose_kernel<<<dim3(24, 24, L_), 256>>>(kw, pkwT, D_, D_);
    transpose_kernel<<<dim3(24, 24, L_), 256>>>(vw, pvwT, D_, D_);
    transpose_kernel<<<dim3(96, 24, L_), 256>>>(w1, pw1T, D_, DFF_);
    transpose_kernel<<<dim3(24, 96, L_), 256>>>(w2, pw2T, DFF_, D_);

    input_proj_kernel<<<MTOK, 256>>>(x, in_w, in_b, pos);

    dim3 gD  (D_   / 128, MTOK / 128);   // (6, 64)
    dim3 gDFF(DFF_ / 128, MTOK / 128);   // (24, 64)
    dim3 gAttn(S_, H_, B_);

    for (int l = 0; l < L_; l++) {
        const float* qwTl = pqwT + (size_t)l * D_ * D_;
        const float* kwTl = pkwT + (size_t)l * D_ * D_;
        const float* vwTl = pvwT + (size_t)l * D_ * D_;
        const float* w1Tl = pw1T + (size_t)l * D_ * DFF_;
        const float* w2Tl = pw2T + (size_t)l * DFF_ * D_;

        gemm_mma<<<gD, 256, SMEM_GEMM>>>(ph, qwTl, qb + l * D_, pq, D_, D_, 0);
        gemm_mma<<<gD, 256, SMEM_GEMM>>>(ph, kwTl, kb + l * D_, pk, D_, D_, 0);
        gemm_mma<<<gD, 256, SMEM_GEMM>>>(ph, vwTl, vb + l * D_, pv, D_, D_, 0);

        attn_kernel<<<gAttn, 128>>>(lens);

        ln_residual_kernel<<<MTOK, 256>>>(po, ln1g + l * D_, ln1b + l * D_);

        gemm_mma<<<gDFF, 256, SMEM_GEMM>>>(ph, w1Tl, b1 + l * DFF_, pff, DFF_, D_, 1);
        gemm_mma<<<gD,   256, SMEM_GEMM>>>(pff, w2Tl, b2 + l * D_,  pt,  D_, DFF_, 0);

        ln_residual_kernel<<<MTOK, 256>>>(pt, ln2g + l * D_, ln2b + l * D_);
    }

    pool_kernel<<<B_, 256>>>(lens, out_w, out_b, out);
}

// round 5
// speedup vs baseline: 5.0529x; 2.0326x over previous
#include <cuda_runtime.h>
#include <math.h>
#include <stdint.h>

#define D_      768
#define DFF_    3072
#define S_      512
#define B_      16
#define H_      12
#define DH_     64
#define L_      6
#define MTOK    (B_ * S_)   // 8192
#define EPS_    1e-5f

// ---------------- scratch (device globals; no allocation allowed) -------------
__device__ float g_h [MTOK * D_];
__device__ float g_q [MTOK * D_];
__device__ float g_k [MTOK * D_];
__device__ float g_v [MTOK * D_];
__device__ float g_o [MTOK * D_];
__device__ float g_t [MTOK * D_];
__device__ float g_ff[MTOK * DFF_];
// transposed weights Wt[N,K] fp32 (pre-rounded to tf32)
__device__ float g_qwT[L_ * D_ * D_];
__device__ float g_kwT[L_ * D_ * D_];
__device__ float g_vwT[L_ * D_ * D_];
__device__ float g_w1T[L_ * D_ * DFF_];
__device__ float g_w2T[L_ * DFF_ * D_];

// ======================= helpers ==============================================
__device__ __forceinline__ uint32_t smem_u32(const void* p) {
    uint32_t a;
    asm("{ .reg .u64 t; cvta.to.shared.u64 t, %1; cvt.u32.u64 %0, t; }" : "=r"(a) : "l"(p));
    return a;
}
__device__ __forceinline__ void cp16(uint32_t saddr, const void* g) {
    asm volatile("cp.async.cg.shared.global [%0], [%1], 16;" :: "r"(saddr), "l"(g));
}
#define CP_COMMIT()  asm volatile("cp.async.commit_group;" ::: "memory")
#define CP_WAIT1()   asm volatile("cp.async.wait_group 1;" ::: "memory")
#define CP_WAIT0()   asm volatile("cp.async.wait_group 0;" ::: "memory")

__device__ __forceinline__ uint32_t f2tf32(float x) {
    uint32_t u;
    asm("cvt.rna.tf32.f32 %0, %1;" : "=r"(u) : "f"(x));
    return u;
}
__device__ __forceinline__ void ldm_x4(uint32_t& r0, uint32_t& r1, uint32_t& r2,
                                       uint32_t& r3, uint32_t addr) {
    asm volatile("ldmatrix.sync.aligned.m8n8.x4.shared.b16 {%0,%1,%2,%3}, [%4];"
                 : "=r"(r0), "=r"(r1), "=r"(r2), "=r"(r3) : "r"(addr));
}
__device__ __forceinline__ void mma_tf32(
    float& c0, float& c1, float& c2, float& c3,
    uint32_t a0, uint32_t a1, uint32_t a2, uint32_t a3,
    uint32_t b0, uint32_t b1)
{
    asm volatile(
        "mma.sync.aligned.m16n8k8.row.col.f32.tf32.tf32.f32 "
        "{%0,%1,%2,%3}, {%4,%5,%6,%7}, {%8,%9}, {%0,%1,%2,%3};"
        : "+f"(c0), "+f"(c1), "+f"(c2), "+f"(c3)
        : "r"(a0), "r"(a1), "r"(a2), "r"(a3), "r"(b0), "r"(b1));
}

// ---------------- GEMM config --------------------------------------------------
#define BM      128
#define BN      128
#define BK      32
#define NSTG    3
#define PAD     36                          // floats per smem row (bank-conflict-free)
#define STG_F   (128 * PAD)                 // floats per tile per stage
#define SMEM_GEMM (2 * NSTG * STG_F * 4)    // 110592 bytes

// ============ tf32 mma.sync GEMM: C[M,N] = A[M,K] @ Wt[N,K]^T + bias ==========
__global__ __launch_bounds__(256) void gemm_mma(
    const float* __restrict__ A, const float* __restrict__ Wt,
    const float* __restrict__ bias, float* __restrict__ C,
    int N, int K, int relu)
{
    extern __shared__ float smem[];
    float* As = smem;
    float* Bs = smem + NSTG * STG_F;
    uint32_t sA = smem_u32(As);
    uint32_t sB = smem_u32(Bs);

    int tid  = threadIdx.x;
    int lane = tid & 31;
    int wid  = tid >> 5;
    int grp  = lane >> 2, tg = lane & 3;
    int bm = blockIdx.y * BM;
    int bn = blockIdx.x * BN;
    int m0 = (wid & 1) * 64;     // warp M offset within tile
    int n0 = (wid >> 1) * 32;    // warp N offset within tile

    uint32_t a_lane = ((((lane >> 3) & 1) * 8 + (lane & 7)) * PAD
                       + ((lane >> 4) & 1) * 4) * 4;
    uint32_t b_lane = ((((lane >> 4) & 1) * 8 + (lane & 7)) * PAD
                       + ((lane >> 3) & 1) * 4) * 4;
    uint32_t aw = sA + (uint32_t)(m0 * PAD) * 4 + a_lane;
    uint32_t bw = sB + (uint32_t)(n0 * PAD) * 4 + b_lane;

    float acc[4][4][4];
    #pragma unroll
    for (int i = 0; i < 4; i++)
        #pragma unroll
        for (int j = 0; j < 4; j++)
            #pragma unroll
            for (int q = 0; q < 4; q++) acc[i][j][q] = 0.f;

    const int nk = K / BK;

    #define LOAD_STAGE(s, k0) do {                                              \
        _Pragma("unroll")                                                       \
        for (int i = 0; i < 4; i++) {                                           \
            int ch = tid + i * 256;          /* 0..1023 */                      \
            int row = ch >> 3, kc = (ch & 7) * 4;                               \
            uint32_t off = (uint32_t)(((s) * STG_F + row * PAD + kc) * 4);      \
            cp16(sA + off, A  + (size_t)(bm + row) * K + (k0) + kc);            \
            cp16(sB + off, Wt + (size_t)(bn + row) * K + (k0) + kc);            \
        }                                                                       \
        CP_COMMIT();                                                            \
    } while (0)

    LOAD_STAGE(0, 0);
    LOAD_STAGE(1, BK);

    for (int step = 0; step < nk; step++) {
        int cur = step % NSTG;
        if (step + 2 <= nk) { CP_WAIT1(); } else { CP_WAIT0(); }
        __syncthreads();

        int nxt = step + 2;
        if (nxt < nk) LOAD_STAGE(nxt % NSTG, nxt * BK);

        uint32_t abase = aw + (uint32_t)(cur * STG_F) * 4;
        uint32_t bbase = bw + (uint32_t)(cur * STG_F) * 4;

        #pragma unroll
        for (int kk = 0; kk < 4; kk++) {          // four k8 sub-steps
            uint32_t kboff = (uint32_t)kk * 32;   // 8 floats = 32 bytes
            uint32_t af[4][4];
            #pragma unroll
            for (int im = 0; im < 4; im++)
                ldm_x4(af[im][0], af[im][1], af[im][2], af[im][3],
                       abase + (uint32_t)(im * 16 * PAD) * 4 + kboff);
            uint32_t bf[4][2];
            ldm_x4(bf[0][0], bf[0][1], bf[1][0], bf[1][1], bbase + kboff);
            ldm_x4(bf[2][0], bf[2][1], bf[3][0], bf[3][1],
                   bbase + (uint32_t)(16 * PAD) * 4 + kboff);
            #pragma unroll
            for (int im = 0; im < 4; im++)
                #pragma unroll
                for (int in_ = 0; in_ < 4; in_++)
                    mma_tf32(acc[im][in_][0], acc[im][in_][1],
                             acc[im][in_][2], acc[im][in_][3],
                             af[im][0], af[im][1], af[im][2], af[im][3],
                             bf[in_][0], bf[in_][1]);
        }
        __syncthreads();
    }

    #pragma unroll
    for (int im = 0; im < 4; im++) {
        int row = bm + m0 + im * 16 + grp;
        #pragma unroll
        for (int in_ = 0; in_ < 4; in_++) {
            int col = bn + n0 + in_ * 8 + tg * 2;
            float2 bv = *(const float2*)&bias[col];
            float2 v0, v1;
            v0.x = acc[im][in_][0] + bv.x;
            v0.y = acc[im][in_][1] + bv.y;
            v1.x = acc[im][in_][2] + bv.x;
            v1.y = acc[im][in_][3] + bv.y;
            if (relu) {
                v0.x = fmaxf(v0.x, 0.f); v0.y = fmaxf(v0.y, 0.f);
                v1.x = fmaxf(v1.x, 0.f); v1.y = fmaxf(v1.y, 0.f);
            }
            *(float2*)&C[(size_t)row * N + col]       = v0;
            *(float2*)&C[(size_t)(row + 8) * N + col] = v1;
        }
    }
    #undef LOAD_STAGE
}

// ---------------- weight transpose (+ tf32 rounding) ---------------------------
__global__ __launch_bounds__(256) void transpose_kernel(
    const float* __restrict__ src, float* __restrict__ dst, int R, int C)
{
    __shared__ float t[32][33];
    src += (size_t)blockIdx.z * R * C;
    dst += (size_t)blockIdx.z * R * C;
    int c0 = blockIdx.x * 32, r0 = blockIdx.y * 32;
    int x = threadIdx.x & 31, y = threadIdx.x >> 5;   // 32 x 8
    #pragma unroll
    for (int i = 0; i < 32; i += 8)
        t[y + i][x] = src[(size_t)(r0 + y + i) * C + c0 + x];
    __syncthreads();
    #pragma unroll
    for (int i = 0; i < 32; i += 8)
        dst[(size_t)(c0 + y + i) * R + r0 + x] = __uint_as_float(f2tf32(t[x][y + i]));
}

// merged QKV transpose: z = mat*L + layer, mat in {0,1,2}
__global__ __launch_bounds__(256) void transpose_qkv_kernel(
    const float* __restrict__ qw, const float* __restrict__ kw,
    const float* __restrict__ vw)
{
    __shared__ float t[32][33];
    int mat = blockIdx.z / L_, l = blockIdx.z % L_;
    const float* src = (mat == 0 ? qw : mat == 1 ? kw : vw) + (size_t)l * D_ * D_;
    float* dst = (mat == 0 ? g_qwT : mat == 1 ? g_kwT : g_vwT) + (size_t)l * D_ * D_;
    int c0 = blockIdx.x * 32, r0 = blockIdx.y * 32;
    int x = threadIdx.x & 31, y = threadIdx.x >> 5;
    #pragma unroll
    for (int i = 0; i < 32; i += 8)
        t[y + i][x] = src[(size_t)(r0 + y + i) * D_ + c0 + x];
    __syncthreads();
    #pragma unroll
    for (int i = 0; i < 32; i += 8)
        dst[(size_t)(c0 + y + i) * D_ + r0 + x] = __uint_as_float(f2tf32(t[x][y + i]));
}

// ---------------- block reductions ---------------------------------------------
__device__ __forceinline__ float block_sum(float v, float* sred) {
    #pragma unroll
    for (int o = 16; o > 0; o >>= 1) v += __shfl_xor_sync(0xffffffffu, v, o);
    int wid = threadIdx.x >> 5, lid = threadIdx.x & 31;
    int nw = (blockDim.x + 31) >> 5;
    __syncthreads();
    if (lid == 0) sred[wid] = v;
    __syncthreads();
    if (wid == 0) {
        float t = (lid < nw) ? sred[lid] : 0.f;
        #pragma unroll
        for (int o = 16; o > 0; o >>= 1) t += __shfl_xor_sync(0xffffffffu, t, o);
        if (lid == 0) sred[0] = t;
    }
    __syncthreads();
    return sred[0];
}

// ---------------- input projection ---------------------------------------------
__global__ __launch_bounds__(256) void input_proj_kernel(
    const float* __restrict__ x, const float* __restrict__ in_w,
    const float* __restrict__ in_b, const float* __restrict__ pos)
{
    int t = blockIdx.x;
    int s = t & (S_ - 1);
    __shared__ float sx[32];
    if (threadIdx.x < 32) sx[threadIdx.x] = x[t * 32 + threadIdx.x];
    __syncthreads();
    for (int d = threadIdx.x; d < D_; d += 256) {
        float acc = in_b[d] + pos[s * D_ + d];
        #pragma unroll
        for (int kk = 0; kk < 32; kk++) acc = fmaf(sx[kk], in_w[kk * D_ + d], acc);
        g_h[t * D_ + d] = acc;
    }
}

// ---------------- flash attention: block per (q-tile 128, head, batch) ----------
#define QT   128
#define KTA  16

__global__ __launch_bounds__(128) void attn_flash(const int* __restrict__ lens)
{
    int qt = blockIdx.x, h = blockIdx.y, b = blockIdx.z;
    int len = lens[b];
    int qbase = qt * QT;
    if (qbase >= len) return;   // dead tile
    int tid = threadIdx.x;

    __shared__ float Qs[QT][68];
    __shared__ float Ks[KTA][64];
    __shared__ float Vs[KTA][64];

    // cooperative, coalesced Q tile load
    #pragma unroll
    for (int i = 0; i < 16; i++) {
        int c = tid + i * 128;
        int r = c >> 4, col = (c & 15) * 4;
        *(float4*)&Qs[r][col] =
            *(const float4*)(g_q + (size_t)(b * S_ + qbase + r) * D_ + h * 64 + col);
    }
    __syncthreads();

    float4 qv[16];
    #pragma unroll
    for (int j = 0; j < 16; j++) qv[j] = *(const float4*)&Qs[tid][j * 4];

    bool valid = (qbase + tid) < len;
    float m = -1e30f, l = 0.f;
    float4 O[16];
    #pragma unroll
    for (int j = 0; j < 16; j++) O[j] = make_float4(0.f, 0.f, 0.f, 0.f);

    int nkt = (len + KTA - 1) / KTA;
    for (int kt = 0; kt < nkt; kt++) {
        int kbase = kt * KTA;
        __syncthreads();
        // cooperative K/V tile load: 16 rows x 64 floats each
        {
            int r = tid >> 3, col = (tid & 7) * 4;   // 128 thr = 16 rows x 8 chunks... r<16 col<32
            // two half-rows per thread to cover 64 cols
            size_t g = (size_t)(b * S_ + kbase + r) * D_ + h * 64 + col;
            *(float4*)&Ks[r][col]      = *(const float4*)(g_k + g);
            *(float4*)&Ks[r][col + 32] = *(const float4*)(g_k + g + 32);
            *(float4*)&Vs[r][col]      = *(const float4*)(g_v + g);
            *(float4*)&Vs[r][col + 32] = *(const float4*)(g_v + g + 32);
        }
        __syncthreads();
        if (!valid) continue;

        int krem = len - kbase;
        float s[KTA];
        #pragma unroll
        for (int k = 0; k < KTA; k++) {
            float acc = 0.f;
            const float4* kr = (const float4*)&Ks[k][0];
            #pragma unroll
            for (int j = 0; j < 16; j++) {
                float4 kv = kr[j];
                acc = fmaf(kv.x, qv[j].x, acc);
                acc = fmaf(kv.y, qv[j].y, acc);
                acc = fmaf(kv.z, qv[j].z, acc);
                acc = fmaf(kv.w, qv[j].w, acc);
            }
            s[k] = (k < krem) ? acc * 0.125f : -1e30f;
        }
        float tmax = m;
        #pragma unroll
        for (int k = 0; k < KTA; k++) tmax = fmaxf(tmax, s[k]);
        float scale = __expf(m - tmax);
        float psum = 0.f;
        #pragma unroll
        for (int k = 0; k < KTA; k++) { s[k] = __expf(s[k] - tmax); psum += s[k]; }
        l = l * scale + psum;
        m = tmax;
        #pragma unroll
        for (int j = 0; j < 16; j++) {
            float4 o = O[j];
            o.x *= scale; o.y *= scale; o.z *= scale; o.w *= scale;
            #pragma unroll
            for (int k = 0; k < KTA; k++) {
                float4 vv = *(const float4*)&Vs[k][j * 4];
                o.x = fmaf(s[k], vv.x, o.x);
                o.y = fmaf(s[k], vv.y, o.y);
                o.z = fmaf(s[k], vv.z, o.z);
                o.w = fmaf(s[k], vv.w, o.w);
            }
            O[j] = o;
        }
    }

    if (valid) {
        float inv = 1.f / l;
        float* orow = g_o + (size_t)(b * S_ + qbase + tid) * D_ + h * 64;
        #pragma unroll
        for (int j = 0; j < 16; j++) {
            float4 o = O[j];
            o.x *= inv; o.y *= inv; o.z *= inv; o.w *= inv;
            *(float4*)(orow + j * 4) = o;
        }
    }
}

// ---------------- fused residual + layernorm ------------------------------------
__global__ __launch_bounds__(256) void ln_residual_kernel(
    const float* __restrict__ res, const float* __restrict__ gma,
    const float* __restrict__ bta)
{
    int t = blockIdx.x;
    int tid = threadIdx.x;
    __shared__ float sred[32];

    float vals[3];
    float s = 0.f;
    #pragma unroll
    for (int i = 0; i < 3; i++) {
        int d = tid + i * 256;
        float v = g_h[(size_t)t * D_ + d] + res[(size_t)t * D_ + d];
        vals[i] = v;
        s += v;
    }
    float mean = block_sum(s, sred) * (1.f / D_);

    float sq = 0.f;
    #pragma unroll
    for (int i = 0; i < 3; i++) { float c = vals[i] - mean; sq += c * c; }
    float var = block_sum(sq, sred) * (1.f / D_);
    float invstd = rsqrtf(var + EPS_);

    #pragma unroll
    for (int i = 0; i < 3; i++) {
        int d = tid + i * 256;
        g_h[(size_t)t * D_ + d] = (vals[i] - mean) * invstd * gma[d] + bta[d];
    }
}

// ---------------- pooling + output projection -----------------------------------
__global__ __launch_bounds__(256) void pool_kernel(
    const int* __restrict__ lens, const float* __restrict__ out_w,
    const float* __restrict__ out_b, float* __restrict__ out)
{
    int b = blockIdx.x;
    int tid = threadIdx.x;
    int len = lens[b];
    __shared__ float sred[32];

    float acc = 0.f;
    float invlen = 1.f / (float)len;
    #pragma unroll
    for (int i = 0; i < 3; i++) {
        int d = tid + i * 256;
        float s = 0.f;
        for (int si = 0; si < len; si++)
            s += g_h[(size_t)(b * S_ + si) * D_ + d];
        acc += (s * invlen) * out_w[d];
    }
    float tot = block_sum(acc, sred);
    if (tid == 0) out[b] = tot + out_b[0];
}

// ---------------- launch ---------------------------------------------------------
extern "C" void kernel_launch(void* const* d_in, const int* in_sizes, int n_in,
                              void* d_out, int out_size)
{
    const float* x     = (const float*)d_in[0];
    const int*   lens  = (const int*)  d_in[1];
    const float* in_w  = (const float*)d_in[2];
    const float* in_b  = (const float*)d_in[3];
    const float* pos   = (const float*)d_in[4];
    const float* qw    = (const float*)d_in[5];
    const float* qb    = (const float*)d_in[6];
    const float* kw    = (const float*)d_in[7];
    const float* kb    = (const float*)d_in[8];
    const float* vw    = (const float*)d_in[9];
    const float* vb    = (const float*)d_in[10];
    const float* w1    = (const float*)d_in[11];
    const float* b1    = (const float*)d_in[12];
    const float* w2    = (const float*)d_in[13];
    const float* b2    = (const float*)d_in[14];
    const float* ln1g  = (const float*)d_in[15];
    const float* ln1b  = (const float*)d_in[16];
    const float* ln2g  = (const float*)d_in[17];
    const float* ln2b  = (const float*)d_in[18];
    const float* out_w = (const float*)d_in[19];
    const float* out_b = (const float*)d_in[20];
    float* out = (float*)d_out;

    float *ph, *pq, *pk, *pv, *po, *pt, *pff;
    float *pqwT, *pkwT, *pvwT, *pw1T, *pw2T;
    cudaGetSymbolAddress((void**)&ph,  g_h);
    cudaGetSymbolAddress((void**)&pq,  g_q);
    cudaGetSymbolAddress((void**)&pk,  g_k);
    cudaGetSymbolAddress((void**)&pv,  g_v);
    cudaGetSymbolAddress((void**)&po,  g_o);
    cudaGetSymbolAddress((void**)&pt,  g_t);
    cudaGetSymbolAddress((void**)&pff, g_ff);
    cudaGetSymbolAddress((void**)&pqwT, g_qwT);
    cudaGetSymbolAddress((void**)&pkwT, g_kwT);
    cudaGetSymbolAddress((void**)&pvwT, g_vwT);
    cudaGetSymbolAddress((void**)&pw1T, g_w1T);
    cudaGetSymbolAddress((void**)&pw2T, g_w2T);

    cudaFuncSetAttribute(gemm_mma, cudaFuncAttributeMaxDynamicSharedMemorySize, SMEM_GEMM);

    // weight transposes: Wt[N,K] = W[K,N]^T, rounded to tf32
    transpose_qkv_kernel<<<dim3(24, 24, 3 * L_), 256>>>(qw, kw, vw);
    transpose_kernel<<<dim3(96, 24, L_), 256>>>(w1, pw1T, D_, DFF_);
    transpose_kernel<<<dim3(24, 96, L_), 256>>>(w2, pw2T, DFF_, D_);

    input_proj_kernel<<<MTOK, 256>>>(x, in_w, in_b, pos);

    dim3 gD  (D_   / 128, MTOK / 128);   // (6, 64)
    dim3 gDFF(DFF_ / 128, MTOK / 128);   // (24, 64)
    dim3 gAttn(S_ / QT, H_, B_);         // (4, 12, 16)

    for (int l = 0; l < L_; l++) {
        const float* qwTl = pqwT + (size_t)l * D_ * D_;
        const float* kwTl = pkwT + (size_t)l * D_ * D_;
        const float* vwTl = pvwT + (size_t)l * D_ * D_;
        const float* w1Tl = pw1T + (size_t)l * D_ * DFF_;
        const float* w2Tl = pw2T + (size_t)l * DFF_ * D_;

        gemm_mma<<<gD, 256, SMEM_GEMM>>>(ph, qwTl, qb + l * D_, pq, D_, D_, 0);
        gemm_mma<<<gD, 256, SMEM_GEMM>>>(ph, kwTl, kb + l * D_, pk, D_, D_, 0);
        gemm_mma<<<gD, 256, SMEM_GEMM>>>(ph, vwTl, vb + l * D_, pv, D_, D_, 0);

        attn_flash<<<gAttn, 128>>>(lens);

        ln_residual_kernel<<<MTOK, 256>>>(po, ln1g + l * D_, ln1b + l * D_);

        gemm_mma<<<gDFF, 256, SMEM_GEMM>>>(ph, w1Tl, b1 + l * DFF_, pff, DFF_, D_, 1);
        gemm_mma<<<gD,   256, SMEM_GEMM>>>(pff, w2Tl, b2 + l * D_,  pt,  D_, DFF_, 0);

        ln_residual_kernel<<<MTOK, 256>>>(pt, ln2g + l * D_, ln2b + l * D_);
    }

    pool_kernel<<<B_, 256>>>(lens, out_w, out_b, out);
}